// round 6
// baseline (speedup 1.0000x reference)
#include <cuda_runtime.h>
#include <cuda_bf16.h>

#define BATCH 16384
#define DIM   4096
#define DIM4  (DIM / 4)          // 1024 float4 column-groups
#define THREADS 256
#define CBLK  (DIM4 / THREADS)   // 4 column blocks
#define RPT   16                 // rows per tile
#define RBLK  (BATCH / RPT)      // 1024 row tiles
#define RUN   4                  // load batch depth
#define SMS   148
#define GRIDY SMS                // persistent: one wave of 4*148 = 592 blocks

__device__ __forceinline__ float fast_ex2(float x) {
    float r; asm("ex2.approx.f32 %0, %1;" : "=f"(r) : "f"(x)); return r;
}
__device__ __forceinline__ float fast_rcp(float x) {
    float r; asm("rcp.approx.f32 %0, %1;" : "=f"(r) : "f"(x)); return r;
}

// Per-column state:
//   exp family  (silu/sigmoid/tanh): out = (u*x + c) * sigmoid(a*x) + d
//   relu family (relu/leaky):        out = max(u*x, x)      (u reused)
struct Col { float u, c, d, k; bool isExp; };

__device__ __forceinline__ Col make_col(int f) {
    const float L2E = 1.4426950408889634f;
    Col o;
    o.isExp = (f == 1) || (f == 3) || (f == 4);
    if (o.isExp) o.u = (f == 1) ? 1.0f : 0.0f;
    else         o.u = (f == 2) ? 0.01f : 0.0f;
    o.c = (f == 3) ? 1.0f : ((f == 4) ? 2.0f : 0.0f);
    o.d = (f == 4) ? -1.0f : 0.0f;
    o.k = (f == 4) ? -2.0f * L2E : -L2E;
    return o;
}

__device__ __forceinline__ float act(float x, const Col& q, float m) {
    float e  = fast_ex2(q.k * x);              // exp(-a*x)
    float s  = fast_rcp(1.0f + e);             // sigmoid(a*x)
    float eo = fmaf(fmaf(q.u, x, q.c), s, q.d);
    float ro = fmaxf(q.u * x, x);
    float r  = q.isExp ? eo : ro;
    return fminf(r, m);
}

__global__ void __launch_bounds__(THREADS, 4)
random_activation_kernel(const float4* __restrict__ x,
                         const float4* __restrict__ max_out,   // [DIM4]
                         const int4*   __restrict__ func_id,   // [DIM4]
                         float4*       __restrict__ out) {
    int c = blockIdx.x * THREADS + threadIdx.x;   // fixed column-group forever

    // Per-column dispatch resolved ONCE per thread for the whole kernel.
    int4   f = func_id[c];
    float4 m = max_out[c];
    Col qx = make_col(f.x);
    Col qy = make_col(f.y);
    Col qz = make_col(f.z);
    Col qw = make_col(f.w);

    // Persistent: grid-stride over row tiles, single wave.
    for (int rb = blockIdx.y; rb < RBLK; rb += GRIDY) {
        const float4* __restrict__ px = x   + (size_t)rb * (RPT * DIM4) + c;
        float4*       __restrict__ po = out + (size_t)rb * (RPT * DIM4) + c;

#pragma unroll
        for (int j0 = 0; j0 < RPT; j0 += RUN) {
            float4 xv[RUN];
#pragma unroll
            for (int j = 0; j < RUN; j++)
                xv[j] = __ldcs(px + (j0 + j) * DIM4);   // LDG.128 [base+imm]

#pragma unroll
            for (int j = 0; j < RUN; j++) {
                float4 r;
                r.x = act(xv[j].x, qx, m.x);
                r.y = act(xv[j].y, qy, m.y);
                r.z = act(xv[j].z, qz, m.z);
                r.w = act(xv[j].w, qw, m.w);
                __stcs(po + (j0 + j) * DIM4, r);        // STG.128 [base+imm]
            }
        }
    }
}

extern "C" void kernel_launch(void* const* d_in, const int* in_sizes, int n_in,
                              void* d_out, int out_size) {
    const float4* x  = (const float4*)d_in[0];
    const float4* mo = (const float4*)d_in[1];
    const int4*   fi = (const int4*)d_in[2];
    float4* out = (float4*)d_out;

    dim3 grid(CBLK, GRIDY);   // (4, 148) = 592 blocks = one full wave
    random_activation_kernel<<<grid, THREADS>>>(x, mo, fi, out);
}

// round 7
// speedup vs baseline: 1.1474x; 1.1474x over previous
#include <cuda_runtime.h>
#include <cuda_bf16.h>

#define BATCH 16384
#define DIM   4096
#define DIM4  (DIM / 4)          // 1024 float4 column-groups
#define THREADS 256
#define CBLK  (DIM4 / THREADS)   // 4 column blocks
#define RPT   4                  // rows per block (one RUN batch)
#define RBLK  (BATCH / RPT)      // 4096 row blocks -> 16384 total blocks
#define RUN   4

__device__ __forceinline__ float fast_ex2(float x) {
    float r; asm("ex2.approx.f32 %0, %1;" : "=f"(r) : "f"(x)); return r;
}
__device__ __forceinline__ float fast_rcp(float x) {
    float r; asm("rcp.approx.f32 %0, %1;" : "=f"(r) : "f"(x)); return r;
}

// Per-column state:
//   exp family  (silu/sigmoid/tanh): out = (u*x + c) * sigmoid(a*x) + d
//   relu family (relu/leaky):        out = max(u*x, x)      (u reused)
struct Col { float u, c, d, k; bool isExp; };

__device__ __forceinline__ Col make_col(int f) {
    const float L2E = 1.4426950408889634f;
    Col o;
    o.isExp = (f == 1) || (f == 3) || (f == 4);
    if (o.isExp) o.u = (f == 1) ? 1.0f : 0.0f;
    else         o.u = (f == 2) ? 0.01f : 0.0f;
    o.c = (f == 3) ? 1.0f : ((f == 4) ? 2.0f : 0.0f);
    o.d = (f == 4) ? -1.0f : 0.0f;
    o.k = (f == 4) ? -2.0f * L2E : -L2E;
    return o;
}

__device__ __forceinline__ float act(float x, const Col& q, float m) {
    float e  = fast_ex2(q.k * x);              // exp(-a*x)
    float s  = fast_rcp(1.0f + e);             // sigmoid(a*x)
    float eo = fmaf(fmaf(q.u, x, q.c), s, q.d);
    float ro = fmaxf(q.u * x, x);
    float r  = q.isExp ? eo : ro;
    return fminf(r, m);
}

__global__ void __launch_bounds__(THREADS)
random_activation_kernel(const float4* __restrict__ x,
                         const float4* __restrict__ max_out,   // [DIM4]
                         const int4*   __restrict__ func_id,   // [DIM4]
                         float4*       __restrict__ out) {
    int c  = blockIdx.x * THREADS + threadIdx.x;   // column-group
    int r0 = blockIdx.y * RPT;

    const float4* __restrict__ px = x   + (size_t)r0 * DIM4 + c;
    float4*       __restrict__ po = out + (size_t)r0 * DIM4 + c;

    // Issue the big streaming loads FIRST (independent of metadata),
    // then the L2-hot metadata loads; all 6 in flight together.
    float4 xv[RUN];
#pragma unroll
    for (int j = 0; j < RUN; j++)
        xv[j] = __ldcs(px + j * DIM4);             // LDG.128 [base+imm]

    int4   f = func_id[c];                          // L2-resident broadcast
    float4 m = max_out[c];

    Col qx = make_col(f.x);
    Col qy = make_col(f.y);
    Col qz = make_col(f.z);
    Col qw = make_col(f.w);

#pragma unroll
    for (int j = 0; j < RUN; j++) {
        float4 r;
        r.x = act(xv[j].x, qx, m.x);
        r.y = act(xv[j].y, qy, m.y);
        r.z = act(xv[j].z, qz, m.z);
        r.w = act(xv[j].w, qw, m.w);
        __stcs(po + j * DIM4, r);                  // STG.128 [base+imm]
    }
}

extern "C" void kernel_launch(void* const* d_in, const int* in_sizes, int n_in,
                              void* d_out, int out_size) {
    const float4* x  = (const float4*)d_in[0];
    const float4* mo = (const float4*)d_in[1];
    const int4*   fi = (const int4*)d_in[2];
    float4* out = (float4*)d_out;

    dim3 grid(CBLK, RBLK);   // (4, 4096) = 16384 blocks
    random_activation_kernel<<<grid, THREADS>>>(x, mo, fi, out);
}